// round 7
// baseline (speedup 1.0000x reference)
#include <cuda_runtime.h>
#include <cuda_bf16.h>
#include <cstdint>

#define BB 4
#define SS 2048
#define EE 1024
#define HH 16
#define DD 64
#define BSROWS (BB * SS)   // 8192

__device__ float g_q[BSROWS * EE];
__device__ float g_k[BSROWS * EE];
__device__ float g_v[BSROWS * EE];
__device__ float g_attn[BSROWS * EE];

// ---------------------------------------------------------------------------
// helpers
// ---------------------------------------------------------------------------
__device__ __forceinline__ uint32_t smem_u32(const void* p) {
    uint32_t a;
    asm("{ .reg .u64 t; cvta.to.shared.u64 t, %1; cvt.u32.u64 %0, t; }" : "=r"(a) : "l"(p));
    return a;
}
__device__ __forceinline__ uint32_t f2tf32(float f) {
    uint32_t r;
    asm("cvt.rna.tf32.f32 %0, %1;" : "=r"(r) : "f"(f));
    return r;
}
__device__ __forceinline__ void cp_async16(uint32_t dst, const void* src) {
    asm volatile("cp.async.ca.shared.global [%0], [%1], 16;" :: "r"(dst), "l"(src));
}
#define CP_COMMIT() asm volatile("cp.async.commit_group;" ::: "memory")
#define CP_WAIT(n)  asm volatile("cp.async.wait_group %0;" :: "n"(n) : "memory")

__device__ __forceinline__ void mma_tf32(float* c, const uint32_t* a, const uint32_t* b) {
    asm volatile(
        "mma.sync.aligned.m16n8k8.row.col.f32.tf32.tf32.f32 "
        "{%0,%1,%2,%3}, {%4,%5,%6,%7}, {%8,%9}, {%0,%1,%2,%3};"
        : "+f"(c[0]), "+f"(c[1]), "+f"(c[2]), "+f"(c[3])
        : "r"(a[0]), "r"(a[1]), "r"(a[2]), "r"(a[3]), "r"(b[0]), "r"(b[1]));
}

// k-group permutation: within each 8-float group store [0,4,1,5,2,6,3,7]
// so logical k and k+4 become adjacent (LDS.64-able fragment pairs).
__device__ __forceinline__ int kperm(int c) {           // c in 0..7
    return 2 * (c & 3) + ((c & 4) >> 2);
}

// ---------------------------------------------------------------------------
// tf32 mma.sync GEMM, cp.async raw + in-place convert&permute pass.
// CTA 128x128, BK=32, 8 warps (2x4), warp tile 64x32.
// ---------------------------------------------------------------------------
#define BK 32
#define SSTR 36
#define TILE_F (128 * SSTR)
#define NCHUNK (EE / BK)

__global__ void __launch_bounds__(256)
gemm_tf32(const float* __restrict__ A, const float* __restrict__ W,
          const float* __restrict__ bias, float* __restrict__ C)
{
    extern __shared__ float sm[];
    const uint32_t smb = smem_u32(sm);

    const int t    = threadIdx.x;
    const int brow = blockIdx.y * 128;
    const int bcol = blockIdx.x * 128;

    const int lane = t & 31;
    const int w    = t >> 5;
    const int wm   = (w & 1) * 64;
    const int wn   = (w >> 1) * 32;
    const int g    = lane >> 2;
    const int tg   = lane & 3;

    const int sr = t >> 1;
    const int sc = (t & 1) * 16;
    const float* Ag = A + (long)(brow + sr) * EE + sc;
    const float* Wg = W + (long)(bcol + sr) * EE + sc;
    const uint32_t sdA = smb + (sr * SSTR + sc) * 4;
    const uint32_t sdW = sdA + TILE_F * 4;

    float acc[4][4][4];
#pragma unroll
    for (int i = 0; i < 4; i++)
#pragma unroll
        for (int j = 0; j < 4; j++)
#pragma unroll
            for (int r = 0; r < 4; r++) acc[i][j][r] = 0.f;

#pragma unroll
    for (int j = 0; j < 4; j++) {
        cp_async16(sdA + j * 16, Ag + j * 4);
        cp_async16(sdW + j * 16, Wg + j * 4);
    }
    CP_COMMIT();

    for (int kc = 0; kc < NCHUNK; kc++) {
        const int cur = kc & 1, nxt = cur ^ 1;

        if (kc + 1 < NCHUNK) {
            const int k0 = (kc + 1) * BK;
            const uint32_t bofs = nxt * 2 * TILE_F * 4;
#pragma unroll
            for (int j = 0; j < 4; j++) {
                cp_async16(sdA + bofs + j * 16, Ag + k0 + j * 4);
                cp_async16(sdW + bofs + j * 16, Wg + k0 + j * 4);
            }
            CP_COMMIT();
            CP_WAIT(1);
        } else {
            CP_WAIT(0);
        }
        __syncthreads();

        // ---- in-place convert & permute: each thread rewrites what it staged
        {
            float* Ab = sm + cur * 2 * TILE_F + sr * SSTR + sc;
            float* Wb = Ab + TILE_F;
            float ta[16], tw[16];
#pragma unroll
            for (int j = 0; j < 4; j++) {
                *(float4*)&ta[j * 4] = *(const float4*)&Ab[j * 4];
                *(float4*)&tw[j * 4] = *(const float4*)&Wb[j * 4];
            }
#pragma unroll
            for (int c = 0; c < 16; c++) {
                const int p = (c & 8) + kperm(c & 7);
                Ab[p] = __uint_as_float(f2tf32(ta[c]));
                Wb[p] = __uint_as_float(f2tf32(tw[c]));
            }
        }
        __syncthreads();

        const float* As = sm + cur * 2 * TILE_F;
        const float* Ws = As + TILE_F;
        const int pa = (wm + g) * SSTR + 2 * tg;
        const int pb = (wn + g) * SSTR + 2 * tg;

#pragma unroll
        for (int kk = 0; kk < 4; kk++) {
            uint32_t af[4][4], bf[4][2];
#pragma unroll
            for (int mt = 0; mt < 4; mt++) {
                const int ib = pa + mt * 16 * SSTR + kk * 8;
                float2 x0 = *(const float2*)&As[ib];
                float2 x1 = *(const float2*)&As[ib + 8 * SSTR];
                af[mt][0] = __float_as_uint(x0.x);
                af[mt][1] = __float_as_uint(x1.x);
                af[mt][2] = __float_as_uint(x0.y);
                af[mt][3] = __float_as_uint(x1.y);
            }
#pragma unroll
            for (int nt = 0; nt < 4; nt++) {
                const int ib = pb + nt * 8 * SSTR + kk * 8;
                float2 y = *(const float2*)&Ws[ib];
                bf[nt][0] = __float_as_uint(y.x);
                bf[nt][1] = __float_as_uint(y.y);
            }
#pragma unroll
            for (int mt = 0; mt < 4; mt++)
#pragma unroll
                for (int nt = 0; nt < 4; nt++)
                    mma_tf32(acc[mt][nt], af[mt], bf[nt]);
        }
        __syncthreads();
    }

#pragma unroll
    for (int mt = 0; mt < 4; mt++) {
#pragma unroll
        for (int nt = 0; nt < 4; nt++) {
            const int row = brow + wm + mt * 16 + g;
            const int col = bcol + wn + nt * 8 + 2 * tg;
            float b0 = 0.f, b1 = 0.f;
            if (bias) { b0 = bias[col]; b1 = bias[col + 1]; }
            *(float2*)(C + (long)row * EE + col) =
                make_float2(acc[mt][nt][0] + b0, acc[mt][nt][1] + b1);
            *(float2*)(C + (long)(row + 8) * EE + col) =
                make_float2(acc[mt][nt][2] + b0, acc[mt][nt][3] + b1);
        }
    }
}

// ---------------------------------------------------------------------------
// Tensor-core flash attention, double-buffered KV + in-place tf32 conversion.
// Block: 128 q-rows, 8 warps x 16 rows. KV tiles of 64.
// K stored k-permuted (LDS.64 pairs); V converted in place (linear).
// ---------------------------------------------------------------------------
#define KSTR 68
#define VSTR 72
#define KVBUF (64 * KSTR + 64 * VSTR)           // floats per KV buffer (8960)
#define NEG_BIG (-1e30f)
#define FLASH_SMEMF (2 * KVBUF + 8 * 16 * KSTR) // 26624 floats

__global__ void __launch_bounds__(256, 2)
flash_tc(const float* __restrict__ Qg, const float* __restrict__ Kg,
         const float* __restrict__ Vg, float* __restrict__ Og)
{
    extern __shared__ float smem[];
    float* Qs = smem;                        // [128][KSTR] staging (over KV bufs)
    float* Ps = smem + 2 * KVBUF;

    const uint32_t smb = smem_u32(smem);
    const int tid = threadIdx.x;
    const int w = tid >> 5, lane = tid & 31;
    const int g = lane >> 2, tg = lane & 3;
    const int qt = blockIdx.x;
    const int b = blockIdx.y / HH, h = blockIdx.y % HH;
    const int wm = w * 16;
    const int qlo = qt * 128 + wm;

    const float* Qb = Qg + (long)b * SS * EE + h * DD;
    const float* Kb = Kg + (long)b * SS * EE + h * DD;
    const float* Vb = Vg + (long)b * SS * EE + h * DD;
    float*       Ob = Og + (long)b * SS * EE + h * DD;

    // ---- stage Q tile raw, extract scaled tf32 fragments ----
    {
        const int r = tid >> 1, c = (tid & 1) * 32;
        const float* src = Qb + (long)(qt * 128 + r) * EE + c;
        const uint32_t dst = smb + (r * KSTR + c) * 4;
#pragma unroll
        for (int j = 0; j < 8; j++) cp_async16(dst + j * 16, src + j * 4);
        CP_COMMIT(); CP_WAIT(0);
    }
    __syncthreads();

    uint32_t qf[8][4];
    const float sc = 0.03125f;   // 1/sqrt(1024) folded into Q
#pragma unroll
    for (int ks = 0; ks < 8; ks++) {
        qf[ks][0] = f2tf32(Qs[(wm + g)     * KSTR + tg     + 8 * ks] * sc);
        qf[ks][1] = f2tf32(Qs[(wm + g + 8) * KSTR + tg     + 8 * ks] * sc);
        qf[ks][2] = f2tf32(Qs[(wm + g)     * KSTR + tg + 4 + 8 * ks] * sc);
        qf[ks][3] = f2tf32(Qs[(wm + g + 8) * KSTR + tg + 4 + 8 * ks] * sc);
    }
    __syncthreads();

    float of[8][4];
#pragma unroll
    for (int i = 0; i < 8; i++)
#pragma unroll
        for (int j = 0; j < 4; j++) of[i][j] = 0.f;
    float m0 = NEG_BIG, m1 = NEG_BIG, l0 = 0.f, l1 = 0.f;
    float* Pw = Ps + w * 16 * KSTR;

    // staging geometry (per thread): K row r cols c..c+15, V same
    const int lr = tid >> 2, lc = (tid & 3) * 16;
    const int ntiles = 2 * qt + 2;

    // prologue: tile 0 -> buf 0
    {
        const float* ksrc = Kb + (long)lr * EE + lc;
        const float* vsrc = Vb + (long)lr * EE + lc;
        const uint32_t kdst = smb + (lr * KSTR + lc) * 4;
        const uint32_t vdst = smb + (64 * KSTR + lr * VSTR + lc) * 4;
#pragma unroll
        for (int j = 0; j < 4; j++) cp_async16(kdst + j * 16, ksrc + j * 4);
#pragma unroll
        for (int j = 0; j < 4; j++) cp_async16(vdst + j * 16, vsrc + j * 4);
        CP_COMMIT();
    }

    for (int kt = 0; kt < ntiles; kt++) {
        const int cur = kt & 1, nxt = cur ^ 1;

        if (kt + 1 < ntiles) {
            const long roff = (long)((kt + 1) * 64 + lr) * EE + lc;
            const uint32_t kdst = smb + (nxt * KVBUF + lr * KSTR + lc) * 4;
            const uint32_t vdst = smb + (nxt * KVBUF + 64 * KSTR + lr * VSTR + lc) * 4;
#pragma unroll
            for (int j = 0; j < 4; j++) cp_async16(kdst + j * 16, Kb + roff + j * 4);
#pragma unroll
            for (int j = 0; j < 4; j++) cp_async16(vdst + j * 16, Vb + roff + j * 4);
            CP_COMMIT();
            CP_WAIT(1);
        } else {
            CP_WAIT(0);
        }
        __syncthreads();

        float* Ks = smem + cur * KVBUF;
        float* Vs = Ks + 64 * KSTR;

        // ---- in-place convert: K permuted, V linear ----
        {
            float* kb = Ks + lr * KSTR + lc;
            float* vb = Vs + lr * VSTR + lc;
            float tk[16], tv[16];
#pragma unroll
            for (int j = 0; j < 4; j++) {
                *(float4*)&tk[j * 4] = *(const float4*)&kb[j * 4];
                *(float4*)&tv[j * 4] = *(const float4*)&vb[j * 4];
            }
#pragma unroll
            for (int c = 0; c < 16; c++) {
                const int p = (c & 8) + kperm(c & 7);
                kb[p] = __uint_as_float(f2tf32(tk[c]));
            }
#pragma unroll
            for (int j = 0; j < 4; j++) {
                float4 vv = make_float4(
                    __uint_as_float(f2tf32(tv[j * 4 + 0])),
                    __uint_as_float(f2tf32(tv[j * 4 + 1])),
                    __uint_as_float(f2tf32(tv[j * 4 + 2])),
                    __uint_as_float(f2tf32(tv[j * 4 + 3])));
                *(float4*)&vb[j * 4] = vv;
            }
        }
        __syncthreads();

        if (kt * 64 <= qlo + 15) {
            // ---- S = Q K^T ----
            float s[8][4];
#pragma unroll
            for (int nt = 0; nt < 8; nt++) {
                float c4[4] = {0.f, 0.f, 0.f, 0.f};
#pragma unroll
                for (int ks = 0; ks < 8; ks++) {
                    float2 kk2 = *(const float2*)&Ks[(nt * 8 + g) * KSTR + ks * 8 + 2 * tg];
                    uint32_t bb[2] = {__float_as_uint(kk2.x), __float_as_uint(kk2.y)};
                    mma_tf32(c4, qf[ks], bb);
                }
                s[nt][0] = c4[0]; s[nt][1] = c4[1]; s[nt][2] = c4[2]; s[nt][3] = c4[3];
            }

            // ---- causal mask ----
            if (kt * 64 + 63 > qlo) {
                const int r0g = qlo + g, r1g = qlo + g + 8;
#pragma unroll
                for (int nt = 0; nt < 8; nt++) {
                    const int col = kt * 64 + nt * 8 + 2 * tg;
                    if (col     > r0g) s[nt][0] = NEG_BIG;
                    if (col + 1 > r0g) s[nt][1] = NEG_BIG;
                    if (col     > r1g) s[nt][2] = NEG_BIG;
                    if (col + 1 > r1g) s[nt][3] = NEG_BIG;
                }
            }

            // ---- online softmax ----
            float a0 = NEG_BIG, a1 = NEG_BIG;
#pragma unroll
            for (int nt = 0; nt < 8; nt++) {
                a0 = fmaxf(a0, fmaxf(s[nt][0], s[nt][1]));
                a1 = fmaxf(a1, fmaxf(s[nt][2], s[nt][3]));
            }
            a0 = fmaxf(a0, __shfl_xor_sync(0xffffffffu, a0, 1));
            a0 = fmaxf(a0, __shfl_xor_sync(0xffffffffu, a0, 2));
            a1 = fmaxf(a1, __shfl_xor_sync(0xffffffffu, a1, 1));
            a1 = fmaxf(a1, __shfl_xor_sync(0xffffffffu, a1, 2));

            const float mn0 = fmaxf(m0, a0), mn1 = fmaxf(m1, a1);
            const float cf0 = __expf(m0 - mn0), cf1 = __expf(m1 - mn1);
            m0 = mn0; m1 = mn1;

            float sum0 = 0.f, sum1 = 0.f;
#pragma unroll
            for (int nt = 0; nt < 8; nt++) {
                float p0 = __expf(s[nt][0] - m0);
                float p1 = __expf(s[nt][1] - m0);
                float p2 = __expf(s[nt][2] - m1);
                float p3 = __expf(s[nt][3] - m1);
                sum0 += p0 + p1; sum1 += p2 + p3;
                *(float2*)&Pw[g       * KSTR + nt * 8 + 2 * tg] = make_float2(p0, p1);
                *(float2*)&Pw[(g + 8) * KSTR + nt * 8 + 2 * tg] = make_float2(p2, p3);
            }
            sum0 += __shfl_xor_sync(0xffffffffu, sum0, 1);
            sum0 += __shfl_xor_sync(0xffffffffu, sum0, 2);
            sum1 += __shfl_xor_sync(0xffffffffu, sum1, 1);
            sum1 += __shfl_xor_sync(0xffffffffu, sum1, 2);
            l0 = l0 * cf0 + sum0;
            l1 = l1 * cf1 + sum1;
#pragma unroll
            for (int nt = 0; nt < 8; nt++) {
                of[nt][0] *= cf0; of[nt][1] *= cf0;
                of[nt][2] *= cf1; of[nt][3] *= cf1;
            }
            __syncwarp();

            // ---- O += P V ----
#pragma unroll
            for (int ks = 0; ks < 8; ks++) {
                uint32_t af[4];
                af[0] = f2tf32(Pw[g       * KSTR + tg     + 8 * ks]);
                af[1] = f2tf32(Pw[(g + 8) * KSTR + tg     + 8 * ks]);
                af[2] = f2tf32(Pw[g       * KSTR + tg + 4 + 8 * ks]);
                af[3] = f2tf32(Pw[(g + 8) * KSTR + tg + 4 + 8 * ks]);
#pragma unroll
                for (int dn = 0; dn < 8; dn++) {
                    uint32_t bb[2];
                    bb[0] = __float_as_uint(Vs[(tg     + 8 * ks) * VSTR + dn * 8 + g]);
                    bb[1] = __float_as_uint(Vs[(tg + 4 + 8 * ks) * VSTR + dn * 8 + g]);
                    mma_tf32(of[dn], af, bb);
                }
            }
        }
        __syncthreads();
    }

    // ---- epilogue ----
    const float i0 = 1.f / l0, i1 = 1.f / l1;
    const int r0g = qt * 128 + wm + g, r1g = r0g + 8;
#pragma unroll
    for (int dn = 0; dn < 8; dn++) {
        const int col = dn * 8 + 2 * tg;
        *(float2*)(Ob + (long)r0g * EE + col) =
            make_float2(of[dn][0] * i0, of[dn][1] * i0);
        *(float2*)(Ob + (long)r1g * EE + col) =
            make_float2(of[dn][2] * i1, of[dn][3] * i1);
    }
}

// ---------------------------------------------------------------------------
extern "C" void kernel_launch(void* const* d_in, const int* in_sizes, int n_in,
                              void* d_out, int out_size)
{
    const float* x  = (const float*)d_in[0];
    const float* Wq = (const float*)d_in[1];
    const float* Wk = (const float*)d_in[2];
    const float* Wv = (const float*)d_in[3];
    const float* Wo = (const float*)d_in[4];
    const float* bo = (const float*)d_in[5];
    float* out = (float*)d_out;

    float *q, *k, *v, *a;
    cudaGetSymbolAddress((void**)&q, g_q);
    cudaGetSymbolAddress((void**)&k, g_k);
    cudaGetSymbolAddress((void**)&v, g_v);
    cudaGetSymbolAddress((void**)&a, g_attn);

    const int gemm_smem = 4 * TILE_F * sizeof(float);   // 73728 B
    cudaFuncSetAttribute(gemm_tf32,
                         cudaFuncAttributeMaxDynamicSharedMemorySize, gemm_smem);

    dim3 gg(EE / 128, BSROWS / 128);   // (8, 64)
    gemm_tf32<<<gg, 256, gemm_smem>>>(x, Wq, nullptr, q);
    gemm_tf32<<<gg, 256, gemm_smem>>>(x, Wk, nullptr, k);
    gemm_tf32<<<gg, 256, gemm_smem>>>(x, Wv, nullptr, v);

    const int flash_smem = FLASH_SMEMF * sizeof(float);  // 106496 B
    cudaFuncSetAttribute(flash_tc,
                         cudaFuncAttributeMaxDynamicSharedMemorySize, flash_smem);
    flash_tc<<<dim3(SS / 128, BB * HH), 256, flash_smem>>>(q, k, v, a);

    gemm_tf32<<<gg, 256, gemm_smem>>>(a, Wo, bo, out);
}

// round 8
// speedup vs baseline: 1.2057x; 1.2057x over previous
#include <cuda_runtime.h>
#include <cuda_bf16.h>
#include <cstdint>

#define BB 4
#define SS 2048
#define EE 1024
#define HH 16
#define DD 64
#define BSROWS (BB * SS)   // 8192

// Scratch (device globals; allocation-free per harness rules).
__device__ float g_q[BSROWS * EE];
__device__ float g_k[BSROWS * EE];
__device__ float g_v[BSROWS * EE];
__device__ float g_attn[BSROWS * EE];
__device__ float g_xc[BSROWS * EE];
__device__ float g_wq[EE * EE];
__device__ float g_wk[EE * EE];
__device__ float g_wv[EE * EE];
__device__ float g_wo[EE * EE];

// ---------------------------------------------------------------------------
// helpers
// ---------------------------------------------------------------------------
__device__ __forceinline__ uint32_t smem_u32(const void* p) {
    uint32_t a;
    asm("{ .reg .u64 t; cvta.to.shared.u64 t, %1; cvt.u32.u64 %0, t; }" : "=r"(a) : "l"(p));
    return a;
}
__device__ __forceinline__ uint32_t f2tf32(float f) {
    uint32_t r;
    asm("cvt.rna.tf32.f32 %0, %1;" : "=r"(r) : "f"(f));
    return r;
}
__device__ __forceinline__ float tfr(float f) {          // tf32-round, keep as float
    return __uint_as_float(f2tf32(f));
}
__device__ __forceinline__ void cp_async16(uint32_t dst, const void* src) {
    asm volatile("cp.async.ca.shared.global [%0], [%1], 16;" :: "r"(dst), "l"(src));
}
#define CP_COMMIT() asm volatile("cp.async.commit_group;" ::: "memory")
#define CP_WAIT(n)  asm volatile("cp.async.wait_group %0;" :: "n"(n) : "memory")

__device__ __forceinline__ void mma_tf32(float* c, const uint32_t* a, const uint32_t* b) {
    asm volatile(
        "mma.sync.aligned.m16n8k8.row.col.f32.tf32.tf32.f32 "
        "{%0,%1,%2,%3}, {%4,%5,%6,%7}, {%8,%9}, {%0,%1,%2,%3};"
        : "+f"(c[0]), "+f"(c[1]), "+f"(c[2]), "+f"(c[3])
        : "r"(a[0]), "r"(a[1]), "r"(a[2]), "r"(a[3]), "r"(b[0]), "r"(b[1]));
}

// k-group permutation: physical layout of each 8-float group = [l0,l4,l1,l5,l2,l6,l3,l7]
// => logical k at phys 2k (k<4), logical k+4 at phys 2k+1. Verified by R7 rel_err.
__device__ __forceinline__ int kperm(int c) { return 2 * (c & 3) + ((c & 4) >> 2); }

// ---------------------------------------------------------------------------
// prep: tf32-round + permute 8-float groups, GMEM -> GMEM (bandwidth-bound)
// ---------------------------------------------------------------------------
__global__ void prep_perm(const float* __restrict__ src, float* __restrict__ dst, int ngroups)
{
    int i = blockIdx.x * blockDim.x + threadIdx.x;
    if (i >= ngroups) return;
    const float4* s = (const float4*)(src + 8L * i);
    float4 a = s[0], b = s[1];
    float4 o0 = make_float4(tfr(a.x), tfr(b.x), tfr(a.y), tfr(b.y));
    float4 o1 = make_float4(tfr(a.z), tfr(b.z), tfr(a.w), tfr(b.w));
    float4* d = (float4*)(dst + 8L * i);
    d[0] = o0; d[1] = o1;
}

// ---------------------------------------------------------------------------
// tf32 mma.sync GEMM on pre-converted (rounded+permuted) A and W.
// CTA 128x128, BK=32, 8 warps (2x4), warp tile 64x32, double-buffered cp.async.
// mode: 0 = fp32 out (+bias), 1 = tf32 permuted out, 2 = tf32 rounded out.
// ---------------------------------------------------------------------------
#define BK 32
#define SSTR 36
#define TILE_F (128 * SSTR)
#define NCHUNK (EE / BK)

__global__ void __launch_bounds__(256)
gemm_tf32(const float* __restrict__ A, const float* __restrict__ W,
          const float* __restrict__ bias, float* __restrict__ C, int mode)
{
    extern __shared__ float sm[];
    const uint32_t smb = smem_u32(sm);

    const int t    = threadIdx.x;
    const int brow = blockIdx.y * 128;
    const int bcol = blockIdx.x * 128;

    const int lane = t & 31;
    const int w    = t >> 5;
    const int wm   = (w & 1) * 64;
    const int wn   = (w >> 1) * 32;
    const int g    = lane >> 2;
    const int tg   = lane & 3;

    const int sr = t >> 1;
    const int sc = (t & 1) * 16;
    const float* Ag = A + (long)(brow + sr) * EE + sc;
    const float* Wg = W + (long)(bcol + sr) * EE + sc;
    const uint32_t sdA = smb + (sr * SSTR + sc) * 4;
    const uint32_t sdW = sdA + TILE_F * 4;

    float acc[4][4][4];
#pragma unroll
    for (int i = 0; i < 4; i++)
#pragma unroll
        for (int j = 0; j < 4; j++)
#pragma unroll
            for (int r = 0; r < 4; r++) acc[i][j][r] = 0.f;

#pragma unroll
    for (int j = 0; j < 4; j++) {
        cp_async16(sdA + j * 16, Ag + j * 4);
        cp_async16(sdW + j * 16, Wg + j * 4);
    }
    CP_COMMIT();

    for (int kc = 0; kc < NCHUNK; kc++) {
        const int cur = kc & 1, nxt = cur ^ 1;

        if (kc + 1 < NCHUNK) {
            const int k0 = (kc + 1) * BK;
            const uint32_t bofs = nxt * 2 * TILE_F * 4;
#pragma unroll
            for (int j = 0; j < 4; j++) {
                cp_async16(sdA + bofs + j * 16, Ag + k0 + j * 4);
                cp_async16(sdW + bofs + j * 16, Wg + k0 + j * 4);
            }
            CP_COMMIT();
            CP_WAIT(1);
        } else {
            CP_WAIT(0);
        }
        __syncthreads();

        const float* As = sm + cur * 2 * TILE_F;
        const float* Ws = As + TILE_F;
        const int pa = (wm + g) * SSTR + 2 * tg;
        const int pb = (wn + g) * SSTR + 2 * tg;

#pragma unroll
        for (int kk = 0; kk < 4; kk++) {
            uint32_t af[4][4], bf[4][2];
#pragma unroll
            for (int mt = 0; mt < 4; mt++) {
                const int ib = pa + mt * 16 * SSTR + kk * 8;
                float2 x0 = *(const float2*)&As[ib];
                float2 x1 = *(const float2*)&As[ib + 8 * SSTR];
                af[mt][0] = __float_as_uint(x0.x);
                af[mt][1] = __float_as_uint(x1.x);
                af[mt][2] = __float_as_uint(x0.y);
                af[mt][3] = __float_as_uint(x1.y);
            }
#pragma unroll
            for (int nt = 0; nt < 4; nt++) {
                const int ib = pb + nt * 8 * SSTR + kk * 8;
                float2 y = *(const float2*)&Ws[ib];
                bf[nt][0] = __float_as_uint(y.x);
                bf[nt][1] = __float_as_uint(y.y);
            }
#pragma unroll
            for (int mt = 0; mt < 4; mt++)
#pragma unroll
                for (int nt = 0; nt < 4; nt++)
                    mma_tf32(acc[mt][nt], af[mt], bf[nt]);
        }
        __syncthreads();
    }

    if (mode == 0) {
#pragma unroll
        for (int mt = 0; mt < 4; mt++)
#pragma unroll
            for (int nt = 0; nt < 4; nt++) {
                const int row = brow + wm + mt * 16 + g;
                const int col = bcol + wn + nt * 8 + 2 * tg;
                float b0 = bias ? bias[col] : 0.f;
                float b1 = bias ? bias[col + 1] : 0.f;
                *(float2*)(C + (long)row * EE + col) =
                    make_float2(acc[mt][nt][0] + b0, acc[mt][nt][1] + b1);
                *(float2*)(C + (long)(row + 8) * EE + col) =
                    make_float2(acc[mt][nt][2] + b0, acc[mt][nt][3] + b1);
            }
    } else if (mode == 1) {      // tf32 rounded + permuted (Q, K, attn-layout)
        const int p0 = kperm(2 * tg), p1 = kperm(2 * tg + 1);
#pragma unroll
        for (int mt = 0; mt < 4; mt++)
#pragma unroll
            for (int nt = 0; nt < 4; nt++) {
                const int row = brow + wm + mt * 16 + g;
                const int cb  = bcol + wn + nt * 8;
                C[(long)row * EE + cb + p0]       = tfr(acc[mt][nt][0]);
                C[(long)row * EE + cb + p1]       = tfr(acc[mt][nt][1]);
                C[(long)(row + 8) * EE + cb + p0] = tfr(acc[mt][nt][2]);
                C[(long)(row + 8) * EE + cb + p1] = tfr(acc[mt][nt][3]);
            }
    } else {                     // tf32 rounded, unpermuted (V)
#pragma unroll
        for (int mt = 0; mt < 4; mt++)
#pragma unroll
            for (int nt = 0; nt < 4; nt++) {
                const int row = brow + wm + mt * 16 + g;
                const int col = bcol + wn + nt * 8 + 2 * tg;
                *(float2*)(C + (long)row * EE + col) =
                    make_float2(tfr(acc[mt][nt][0]), tfr(acc[mt][nt][1]));
                *(float2*)(C + (long)(row + 8) * EE + col) =
                    make_float2(tfr(acc[mt][nt][2]), tfr(acc[mt][nt][3]));
            }
    }
}

// ---------------------------------------------------------------------------
// Tensor-core flash attention on pre-converted Q/K (permuted tf32) and V
// (rounded tf32). Double-buffered KV, no in-kernel conversion passes.
// Output written tf32-rounded + permuted (feeds the Wo GEMM directly).
// ---------------------------------------------------------------------------
#define KST 72
#define VST 72
#define PST 68
#define KVBUF (64 * KST + 64 * VST)              // 9216 floats per buffer
#define NEG_BIG (-1e30f)
#define FLASH_SMEMF (2 * KVBUF + 8 * 16 * PST)   // 27136 floats = 108544 B

__global__ void __launch_bounds__(256, 2)
flash_tc(const float* __restrict__ Qg, const float* __restrict__ Kg,
         const float* __restrict__ Vg, float* __restrict__ Og)
{
    extern __shared__ float smem[];
    float* Qs = smem;                        // [128][KST] staging (over KV bufs)
    float* Ps = smem + 2 * KVBUF;

    const uint32_t smb = smem_u32(smem);
    const int tid = threadIdx.x;
    const int w = tid >> 5, lane = tid & 31;
    const int g = lane >> 2, tg = lane & 3;
    const int qt = blockIdx.x;
    const int b = blockIdx.y / HH, h = blockIdx.y % HH;
    const int wm = w * 16;
    const int qlo = qt * 128 + wm;

    const float* Qb = Qg + (long)b * SS * EE + h * DD;
    const float* Kb = Kg + (long)b * SS * EE + h * DD;
    const float* Vb = Vg + (long)b * SS * EE + h * DD;
    float*       Ob = Og + (long)b * SS * EE + h * DD;

    // ---- stage Q (already rounded+permuted), extract scaled fragments ----
    {
        const int r = tid >> 1, c = (tid & 1) * 32;
        const float* src = Qb + (long)(qt * 128 + r) * EE + c;
        const uint32_t dst = smb + (r * KST + c) * 4;
#pragma unroll
        for (int j = 0; j < 8; j++) cp_async16(dst + j * 16, src + j * 4);
        CP_COMMIT(); CP_WAIT(0);
    }
    __syncthreads();

    uint32_t qf[8][4];
    const float sc = 0.03125f;   // 1/sqrt(1024); x2^-5 keeps tf32 exact
#pragma unroll
    for (int ks = 0; ks < 8; ks++) {
        float2 q0 = *(const float2*)&Qs[(wm + g)     * KST + 8 * ks + 2 * tg];
        float2 q1 = *(const float2*)&Qs[(wm + g + 8) * KST + 8 * ks + 2 * tg];
        qf[ks][0] = __float_as_uint(q0.x * sc);
        qf[ks][1] = __float_as_uint(q1.x * sc);
        qf[ks][2] = __float_as_uint(q0.y * sc);
        qf[ks][3] = __float_as_uint(q1.y * sc);
    }
    __syncthreads();

    float of[8][4];
#pragma unroll
    for (int i = 0; i < 8; i++)
#pragma unroll
        for (int j = 0; j < 4; j++) of[i][j] = 0.f;
    float m0 = NEG_BIG, m1 = NEG_BIG, l0 = 0.f, l1 = 0.f;
    float* Pw = Ps + w * 16 * PST;

    const int lr = tid >> 2, lc = (tid & 3) * 16;
    const int ntiles = 2 * qt + 2;

    // prologue: tile 0 -> buf 0
    {
        const float* ksrc = Kb + (long)lr * EE + lc;
        const float* vsrc = Vb + (long)lr * EE + lc;
        const uint32_t kdst = smb + (lr * KST + lc) * 4;
        const uint32_t vdst = smb + (64 * KST + lr * VST + lc) * 4;
#pragma unroll
        for (int j = 0; j < 4; j++) cp_async16(kdst + j * 16, ksrc + j * 4);
#pragma unroll
        for (int j = 0; j < 4; j++) cp_async16(vdst + j * 16, vsrc + j * 4);
        CP_COMMIT();
    }

    for (int kt = 0; kt < ntiles; kt++) {
        const int cur = kt & 1, nxt = cur ^ 1;

        if (kt + 1 < ntiles) {
            const long roff = (long)((kt + 1) * 64 + lr) * EE + lc;
            const uint32_t kdst = smb + (nxt * KVBUF + lr * KST + lc) * 4;
            const uint32_t vdst = smb + (nxt * KVBUF + 64 * KST + lr * VST + lc) * 4;
#pragma unroll
            for (int j = 0; j < 4; j++) cp_async16(kdst + j * 16, Kb + roff + j * 4);
#pragma unroll
            for (int j = 0; j < 4; j++) cp_async16(vdst + j * 16, Vb + roff + j * 4);
            CP_COMMIT();
            CP_WAIT(1);
        } else {
            CP_WAIT(0);
        }
        __syncthreads();

        const float* Ks = smem + cur * KVBUF;
        const float* Vs = Ks + 64 * KST;

        if (kt * 64 <= qlo + 15) {
            // ---- S = Q K^T ----
            float s[8][4];
#pragma unroll
            for (int nt = 0; nt < 8; nt++) {
                float c4[4] = {0.f, 0.f, 0.f, 0.f};
#pragma unroll
                for (int ks = 0; ks < 8; ks++) {
                    float2 kk2 = *(const float2*)&Ks[(nt * 8 + g) * KST + ks * 8 + 2 * tg];
                    uint32_t bb[2] = {__float_as_uint(kk2.x), __float_as_uint(kk2.y)};
                    mma_tf32(c4, qf[ks], bb);
                }
                s[nt][0] = c4[0]; s[nt][1] = c4[1]; s[nt][2] = c4[2]; s[nt][3] = c4[3];
            }

            // ---- causal mask ----
            if (kt * 64 + 63 > qlo) {
                const int r0g = qlo + g, r1g = qlo + g + 8;
#pragma unroll
                for (int nt = 0; nt < 8; nt++) {
                    const int col = kt * 64 + nt * 8 + 2 * tg;
                    if (col     > r0g) s[nt][0] = NEG_BIG;
                    if (col + 1 > r0g) s[nt][1] = NEG_BIG;
                    if (col     > r1g) s[nt][2] = NEG_BIG;
                    if (col + 1 > r1g) s[nt][3] = NEG_BIG;
                }
            }

            // ---- online softmax ----
            float a0 = NEG_BIG, a1 = NEG_BIG;
#pragma unroll
            for (int nt = 0; nt < 8; nt++) {
                a0 = fmaxf(a0, fmaxf(s[nt][0], s[nt][1]));
                a1 = fmaxf(a1, fmaxf(s[nt][2], s[nt][3]));
            }
            a0 = fmaxf(a0, __shfl_xor_sync(0xffffffffu, a0, 1));
            a0 = fmaxf(a0, __shfl_xor_sync(0xffffffffu, a0, 2));
            a1 = fmaxf(a1, __shfl_xor_sync(0xffffffffu, a1, 1));
            a1 = fmaxf(a1, __shfl_xor_sync(0xffffffffu, a1, 2));

            const float mn0 = fmaxf(m0, a0), mn1 = fmaxf(m1, a1);
            const float cf0 = __expf(m0 - mn0), cf1 = __expf(m1 - mn1);
            m0 = mn0; m1 = mn1;

            float sum0 = 0.f, sum1 = 0.f;
#pragma unroll
            for (int nt = 0; nt < 8; nt++) {
                float p0 = __expf(s[nt][0] - m0);
                float p1 = __expf(s[nt][1] - m0);
                float p2 = __expf(s[nt][2] - m1);
                float p3 = __expf(s[nt][3] - m1);
                sum0 += p0 + p1; sum1 += p2 + p3;
                *(float2*)&Pw[g       * PST + nt * 8 + 2 * tg] = make_float2(p0, p1);
                *(float2*)&Pw[(g + 8) * PST + nt * 8 + 2 * tg] = make_float2(p2, p3);
            }
            sum0 += __shfl_xor_sync(0xffffffffu, sum0, 1);
            sum0 += __shfl_xor_sync(0xffffffffu, sum0, 2);
            sum1 += __shfl_xor_sync(0xffffffffu, sum1, 1);
            sum1 += __shfl_xor_sync(0xffffffffu, sum1, 2);
            l0 = l0 * cf0 + sum0;
            l1 = l1 * cf1 + sum1;
#pragma unroll
            for (int nt = 0; nt < 8; nt++) {
                of[nt][0] *= cf0; of[nt][1] *= cf0;
                of[nt][2] *= cf1; of[nt][3] *= cf1;
            }
            __syncwarp();

            // ---- O += P V ----
#pragma unroll
            for (int ks = 0; ks < 8; ks++) {
                uint32_t af[4];
                af[0] = f2tf32(Pw[g       * PST + tg     + 8 * ks]);
                af[1] = f2tf32(Pw[(g + 8) * PST + tg     + 8 * ks]);
                af[2] = f2tf32(Pw[g       * PST + tg + 4 + 8 * ks]);
                af[3] = f2tf32(Pw[(g + 8) * PST + tg + 4 + 8 * ks]);
#pragma unroll
                for (int dn = 0; dn < 8; dn++) {
                    uint32_t bb[2];
                    bb[0] = __float_as_uint(Vs[(tg     + 8 * ks) * VST + dn * 8 + g]);
                    bb[1] = __float_as_uint(Vs[(tg + 4 + 8 * ks) * VST + dn * 8 + g]);
                    mma_tf32(of[dn], af, bb);
                }
            }
        }
        __syncthreads();
    }

    // ---- epilogue: normalize, round, permute-store (feeds Wo GEMM) ----
    const float i0 = 1.f / l0, i1 = 1.f / l1;
    const int r0g = qt * 128 + wm + g, r1g = r0g + 8;
    const int p0 = kperm(2 * tg), p1 = kperm(2 * tg + 1);
#pragma unroll
    for (int dn = 0; dn < 8; dn++) {
        const int cb = dn * 8;
        Ob[(long)r0g * EE + cb + p0] = tfr(of[dn][0] * i0);
        Ob[(long)r0g * EE + cb + p1] = tfr(of[dn][1] * i0);
        Ob[(long)r1g * EE + cb + p0] = tfr(of[dn][2] * i1);
        Ob[(long)r1g * EE + cb + p1] = tfr(of[dn][3] * i1);
    }
}

// ---------------------------------------------------------------------------
extern "C" void kernel_launch(void* const* d_in, const int* in_sizes, int n_in,
                              void* d_out, int out_size)
{
    const float* x  = (const float*)d_in[0];
    const float* Wq = (const float*)d_in[1];
    const float* Wk = (const float*)d_in[2];
    const float* Wv = (const float*)d_in[3];
    const float* Wo = (const float*)d_in[4];
    const float* bo = (const float*)d_in[5];
    float* out = (float*)d_out;

    float *q, *k, *v, *a, *xc, *wq, *wk, *wv, *wo;
    cudaGetSymbolAddress((void**)&q,  g_q);
    cudaGetSymbolAddress((void**)&k,  g_k);
    cudaGetSymbolAddress((void**)&v,  g_v);
    cudaGetSymbolAddress((void**)&a,  g_attn);
    cudaGetSymbolAddress((void**)&xc, g_xc);
    cudaGetSymbolAddress((void**)&wq, g_wq);
    cudaGetSymbolAddress((void**)&wk, g_wk);
    cudaGetSymbolAddress((void**)&wv, g_wv);
    cudaGetSymbolAddress((void**)&wo, g_wo);

    // prep: round+permute x and all weights
    const int xg = BSROWS * EE / 8, wg = EE * EE / 8;
    prep_perm<<<(xg + 255) / 256, 256>>>(x,  xc, xg);
    prep_perm<<<(wg + 255) / 256, 256>>>(Wq, wq, wg);
    prep_perm<<<(wg + 255) / 256, 256>>>(Wk, wk, wg);
    prep_perm<<<(wg + 255) / 256, 256>>>(Wv, wv, wg);
    prep_perm<<<(wg + 255) / 256, 256>>>(Wo, wo, wg);

    const int gemm_smem = 4 * TILE_F * sizeof(float);   // 73728 B
    cudaFuncSetAttribute(gemm_tf32,
                         cudaFuncAttributeMaxDynamicSharedMemorySize, gemm_smem);

    dim3 gg(EE / 128, BSROWS / 128);   // (8, 64)
    gemm_tf32<<<gg, 256, gemm_smem>>>(xc, wq, nullptr, q, 1);   // Q: perm tf32
    gemm_tf32<<<gg, 256, gemm_smem>>>(xc, wk, nullptr, k, 1);   // K: perm tf32
    gemm_tf32<<<gg, 256, gemm_smem>>>(xc, wv, nullptr, v, 2);   // V: tf32

    const int flash_smem = FLASH_SMEMF * sizeof(float);  // 108544 B
    cudaFuncSetAttribute(flash_tc,
                         cudaFuncAttributeMaxDynamicSharedMemorySize, flash_smem);
    flash_tc<<<dim3(SS / 128, BB * HH), 256, flash_smem>>>(q, k, v, a);

    gemm_tf32<<<gg, 256, gemm_smem>>>(a, wo, bo, out, 0);       // out: fp32+bias
}